// round 2
// baseline (speedup 1.0000x reference)
#include <cuda_runtime.h>

// Problem constants
#define BATCH   32768
#define HID     128
#define INF     784
#define NCLS    10
#define TSTEPS  20

#define DECAYF     0.25f
#define THRESHF    1.0f

typedef unsigned long long ull;

// ---- packed f32x2 helpers (lane0 = low 32 bits) --------------------------
__device__ __forceinline__ ull pack2(float lo, float hi) {
    ull r;
    asm("mov.b64 %0, {%1, %2};" : "=l"(r) : "f"(lo), "f"(hi));
    return r;
}
__device__ __forceinline__ void unpack2(ull v, float& lo, float& hi) {
    asm("mov.b64 {%0, %1}, %2;" : "=f"(lo), "=f"(hi) : "l"(v));
}
// d = a*b + d   (two independent IEEE-RN fp32 FMAs)
__device__ __forceinline__ void fma2_acc(ull& d, ull a, ull b) {
    asm("fma.rn.f32x2 %0, %1, %2, %0;" : "+l"(d) : "l"(a), "l"(b));
}
// d = a*b + c
__device__ __forceinline__ ull fma2(ull a, ull b, ull c) {
    ull d;
    asm("fma.rn.f32x2 %0, %1, %2, %3;" : "=l"(d) : "l"(a), "l"(b), "l"(c));
    return d;
}

// ---------------------------------------------------------------------------
// K1 fused: cur1 = x @ W1^T + b1 (M=32768,N=128,K=784) via f32x2 FMA,
// then the 20-step layer-1 LIF loop in the epilogue, writing spk1_rec
// directly (t-major [T,B,H]). Tile 128x128, 256 threads, 8x8 per thread.
// ---------------------------------------------------------------------------
__global__ __launch_bounds__(256) void k1_fused(
    const float* __restrict__ x, const float* __restrict__ W1,
    const float* __restrict__ b1, float* __restrict__ out_spk)
{
    __shared__ float As[16][128];   // [k][m]
    __shared__ float Bs[16][128];   // [k][n]

    const int tid = threadIdx.x;
    const int tx  = tid & 15;       // n group (8 channels)
    const int ty  = tid >> 4;       // m group (8 batch rows)
    const int m0  = blockIdx.x * 128;

    ull acc2[8][4];                 // [row][n-pair]; lanes = (j even, j odd)
    #pragma unroll
    for (int i = 0; i < 8; i++)
        #pragma unroll
        for (int p = 0; p < 4; p++) acc2[i][p] = 0ull;

    for (int k0 = 0; k0 < INF; k0 += 16) {
        // Stage A tile: x[m0+m][k0..k0+15]  (2048 floats = 512 float4)
        #pragma unroll
        for (int it = 0; it < 2; it++) {
            int f  = tid + it * 256;
            int m  = f >> 2;
            int kq = (f & 3) * 4;
            float4 v = *reinterpret_cast<const float4*>(&x[(size_t)(m0 + m) * INF + k0 + kq]);
            As[kq + 0][m] = v.x; As[kq + 1][m] = v.y;
            As[kq + 2][m] = v.z; As[kq + 3][m] = v.w;
        }
        // Stage B tile: W1[n][k0..k0+15]
        #pragma unroll
        for (int it = 0; it < 2; it++) {
            int f  = tid + it * 256;
            int n  = f >> 2;
            int kq = (f & 3) * 4;
            float4 v = *reinterpret_cast<const float4*>(&W1[(size_t)n * INF + k0 + kq]);
            Bs[kq + 0][n] = v.x; Bs[kq + 1][n] = v.y;
            Bs[kq + 2][n] = v.z; Bs[kq + 3][n] = v.w;
        }
        __syncthreads();

        #pragma unroll
        for (int k = 0; k < 16; k++) {
            float4 a0 = *reinterpret_cast<const float4*>(&As[k][ty * 8]);
            float4 a1 = *reinterpret_cast<const float4*>(&As[k][ty * 8 + 4]);
            // b pairs: consecutive j packed (matches acc2 lane layout)
            ulonglong2 bq0 = *reinterpret_cast<const ulonglong2*>(&Bs[k][tx * 8]);
            ulonglong2 bq1 = *reinterpret_cast<const ulonglong2*>(&Bs[k][tx * 8 + 4]);
            ull b2v[4] = {bq0.x, bq0.y, bq1.x, bq1.y};
            float a[8] = {a0.x, a0.y, a0.z, a0.w, a1.x, a1.y, a1.z, a1.w};
            #pragma unroll
            for (int i = 0; i < 8; i++) {
                ull ai = pack2(a[i], a[i]);
                #pragma unroll
                for (int p = 0; p < 4; p++)
                    fma2_acc(acc2[i][p], ai, b2v[p]);
            }
        }
        __syncthreads();
    }

    // ---- epilogue: cur1 = acc + b1, then 20-step LIF, write spikes ----
    float bb[8];
    #pragma unroll
    for (int j = 0; j < 8; j++) bb[j] = __ldg(&b1[tx * 8 + j]);

    float cur[8][8];
    #pragma unroll
    for (int i = 0; i < 8; i++)
        #pragma unroll
        for (int p = 0; p < 4; p++) {
            float lo, hi;
            unpack2(acc2[i][p], lo, hi);
            cur[i][2 * p]     = lo + bb[2 * p];
            cur[i][2 * p + 1] = hi + bb[2 * p + 1];
        }

    float mem[8][8];
    #pragma unroll
    for (int i = 0; i < 8; i++)
        #pragma unroll
        for (int j = 0; j < 8; j++) mem[i][j] = 0.0f;

    // base address for this thread's first row/col
    float* base = out_spk + (size_t)(m0 + ty * 8) * HID + tx * 8;

    for (int t = 0; t < TSTEPS; t++) {
        float* pt = base + (size_t)t * (BATCH * HID);
        #pragma unroll
        for (int i = 0; i < 8; i++) {
            float4 s0, s1;
            float s[8];
            #pragma unroll
            for (int j = 0; j < 8; j++) {
                mem[i][j] = fmaf(mem[i][j], DECAYF, cur[i][j]);   // mem*0.25+cur
                s[j] = (mem[i][j] > THRESHF) ? 1.0f : 0.0f;
                mem[i][j] = (s[j] != 0.0f) ? 0.0f : mem[i][j];
            }
            s0.x = s[0]; s0.y = s[1]; s0.z = s[2]; s0.w = s[3];
            s1.x = s[4]; s1.y = s[5]; s1.z = s[6]; s1.w = s[7];
            float* pr = pt + (size_t)i * HID;
            *reinterpret_cast<float4*>(pr)     = s0;
            *reinterpret_cast<float4*>(pr + 4) = s1;
        }
    }
}

// ---------------------------------------------------------------------------
// K34 fused: for each batch row, loop t: c2 = spk[t,row,:] @ W2^T (f32x2,
// o-pairs), then layer-2 LIF recurrence; accumulate spike counts -> output.
// Block = 256 rows, smem-staged 32-ch chunks (coalesced reads of spk).
// ---------------------------------------------------------------------------
__global__ __launch_bounds__(256) void k34_fused(
    const float* __restrict__ spk, const float* __restrict__ W2,
    const float* __restrict__ b2, float* __restrict__ outp)
{
    __shared__ float sh[256][33];       // pad: conflict-free row reads
    __shared__ ull   W2p[HID][NCLS / 2]; // [j][o-pair] packed (o even, o odd)

    const int tid = threadIdx.x;

    // Stage W2 transposed+packed: W2p[j][p] = (W2[2p][j], W2[2p+1][j])
    for (int f = tid; f < HID * (NCLS / 2); f += 256) {
        int j = f / (NCLS / 2);
        int p = f % (NCLS / 2);
        W2p[j][p] = pack2(W2[(2 * p) * HID + j], W2[(2 * p + 1) * HID + j]);
    }

    float bias[NCLS];
    #pragma unroll
    for (int o = 0; o < NCLS; o++) bias[o] = __ldg(&b2[o]);

    const size_t row0 = (size_t)blockIdx.x * 256;

    float mem[NCLS], sum[NCLS];
    #pragma unroll
    for (int o = 0; o < NCLS; o++) { mem[o] = 0.0f; sum[o] = 0.0f; }

    for (int t = 0; t < TSTEPS; t++) {
        const float* spkt = spk + (size_t)t * (BATCH * HID);
        ull acc2[NCLS / 2];
        #pragma unroll
        for (int p = 0; p < NCLS / 2; p++) acc2[p] = 0ull;

        for (int jc = 0; jc < 4; jc++) {
            __syncthreads();
            #pragma unroll
            for (int s4 = 0; s4 < 8; s4++) {
                int f = tid + s4 * 256;    // 0..2047 float4 slots
                int r = f >> 3;
                int q = f & 7;
                float4 v = *reinterpret_cast<const float4*>(
                    &spkt[(row0 + r) * HID + jc * 32 + q * 4]);
                sh[r][q * 4 + 0] = v.x; sh[r][q * 4 + 1] = v.y;
                sh[r][q * 4 + 2] = v.z; sh[r][q * 4 + 3] = v.w;
            }
            __syncthreads();
            #pragma unroll
            for (int j = 0; j < 32; j++) {
                ull s2 = pack2(sh[tid][j], sh[tid][j]);
                #pragma unroll
                for (int p = 0; p < NCLS / 2; p++)
                    fma2_acc(acc2[p], s2, W2p[jc * 32 + j][p]);
            }
        }

        // LIF2 step (ref order: (mem*0.25 + c2) + b2)
        float c2[NCLS];
        #pragma unroll
        for (int p = 0; p < NCLS / 2; p++)
            unpack2(acc2[p], c2[2 * p], c2[2 * p + 1]);
        #pragma unroll
        for (int o = 0; o < NCLS; o++) {
            float v = fmaf(mem[o], DECAYF, c2[o]);
            v = v + bias[o];
            float s = (v > THRESHF) ? 1.0f : 0.0f;
            sum[o] += s;
            mem[o] = (s != 0.0f) ? 0.0f : v;
        }
    }

    const size_t r = row0 + tid;
    #pragma unroll
    for (int o = 0; o < NCLS; o++)
        outp[r * NCLS + o] = sum[o];
}

// ---------------------------------------------------------------------------
extern "C" void kernel_launch(void* const* d_in, const int* in_sizes, int n_in,
                              void* d_out, int out_size)
{
    const float* x  = (const float*)d_in[0];
    const float* W1 = (const float*)d_in[1];
    const float* b1 = (const float*)d_in[2];
    const float* W2 = (const float*)d_in[3];
    const float* b2 = (const float*)d_in[4];
    float* out = (float*)d_out;

    float* out_output = out;                          // [BATCH, NCLS]
    float* out_spk    = out + (size_t)BATCH * NCLS;   // [T, BATCH, HID]

    k1_fused<<<BATCH / 128, 256>>>(x, W1, b1, out_spk);
    k34_fused<<<BATCH / 256, 256>>>(out_spk, W2, b2, out_output);
}

// round 4
// speedup vs baseline: 1.0807x; 1.0807x over previous
#include <cuda_runtime.h>
#include <cuda_bf16.h>

#define BATCH   32768
#define HID     128
#define INF     784
#define NCLS    10
#define TSTEPS  20

#define DECAYF  0.25f
#define THRESHF 1.0f
#define EPSM    2e-4f

#define KCHUNKS (INF / 16)      // 49
#define FIXCAP  (1 << 21)       // 2M entries

// Scratch (device globals: allocation-free rule)
__device__ float    g_c2[(size_t)TSTEPS * BATCH * NCLS];   // 26.2 MB
__device__ unsigned g_fix_list[FIXCAP];                    // 8 MB
__device__ unsigned g_fix_cnt;

// ---------------------------------------------------------------------------
__device__ __forceinline__ void split3(float v, unsigned short& h0,
                                       unsigned short& h1, unsigned short& h2)
{
    __nv_bfloat16 b0 = __float2bfloat16_rn(v);
    float r1 = v - __bfloat162float(b0);
    __nv_bfloat16 b1 = __float2bfloat16_rn(r1);
    float r2 = r1 - __bfloat162float(b1);
    __nv_bfloat16 b2 = __float2bfloat16_rn(r2);
    h0 = __bfloat16_as_ushort(b0);
    h1 = __bfloat16_as_ushort(b1);
    h2 = __bfloat16_as_ushort(b2);
}

__device__ __forceinline__ void mma_bf16(float* d, const unsigned* a, const unsigned* b)
{
    asm volatile(
        "mma.sync.aligned.m16n8k16.row.col.f32.bf16.bf16.f32 "
        "{%0,%1,%2,%3}, {%4,%5,%6,%7}, {%8,%9}, {%0,%1,%2,%3};"
        : "+f"(d[0]), "+f"(d[1]), "+f"(d[2]), "+f"(d[3])
        : "r"(a[0]), "r"(a[1]), "r"(a[2]), "r"(a[3]), "r"(b[0]), "r"(b[1]));
}

__global__ void k0_zero() { g_fix_cnt = 0; }

// ---------------------------------------------------------------------------
// K1: cur1 via bf16x6 tensor-core emulated fp32, fused 20-step LIF epilogue,
// margin tracking -> fixup list. Tile M=64 x N=128, 256 threads.
// ---------------------------------------------------------------------------
#define ASTRIDE 18

__global__ __launch_bounds__(256) void k1_mma(
    const float* __restrict__ x, const float* __restrict__ W1,
    const float* __restrict__ b1, float* __restrict__ out_spk)
{
    __shared__ unsigned short As[2][3][64  * ASTRIDE];
    __shared__ unsigned short Bs[2][3][128 * ASTRIDE];

    const int tid  = threadIdx.x;
    const int lane = tid & 31;
    const int wid  = tid >> 5;
    const int g    = lane >> 2;
    const int tg   = lane & 3;
    const int wm   = wid >> 2;
    const int wn   = wid & 3;
    const int m0   = blockIdx.x * 64;

    const int sm  = tid >> 2;
    const int skq = (tid & 3) * 4;

    float acc[2][4][4];
    #pragma unroll
    for (int mt = 0; mt < 2; mt++)
        #pragma unroll
        for (int nt = 0; nt < 4; nt++)
            #pragma unroll
            for (int r = 0; r < 4; r++) acc[mt][nt][r] = 0.0f;

    // prologue: stage chunk 0
    {
        float4 ax = *reinterpret_cast<const float4*>(&x[(size_t)(m0 + sm) * INF + skq]);
        float av[4] = {ax.x, ax.y, ax.z, ax.w};
        #pragma unroll
        for (int i = 0; i < 4; i++) {
            unsigned short h0, h1, h2;
            split3(av[i], h0, h1, h2);
            As[0][0][sm * ASTRIDE + skq + i] = h0;
            As[0][1][sm * ASTRIDE + skq + i] = h1;
            As[0][2][sm * ASTRIDE + skq + i] = h2;
        }
        #pragma unroll
        for (int it = 0; it < 2; it++) {
            int f  = tid + it * 256;
            int n  = f >> 2;
            int kq = (f & 3) * 4;
            float4 bx = *reinterpret_cast<const float4*>(&W1[(size_t)n * INF + kq]);
            float bv[4] = {bx.x, bx.y, bx.z, bx.w};
            #pragma unroll
            for (int i = 0; i < 4; i++) {
                unsigned short h0, h1, h2;
                split3(bv[i], h0, h1, h2);
                Bs[0][0][n * ASTRIDE + kq + i] = h0;
                Bs[0][1][n * ASTRIDE + kq + i] = h1;
                Bs[0][2][n * ASTRIDE + kq + i] = h2;
            }
        }
    }
    __syncthreads();

    int buf = 0;
    for (int kc = 0; kc < KCHUNKS; kc++) {
        float4 pax, pbx0, pbx1;
        if (kc < KCHUNKS - 1) {
            int k0 = (kc + 1) * 16;
            pax  = *reinterpret_cast<const float4*>(&x[(size_t)(m0 + sm) * INF + k0 + skq]);
            int n0  = tid >> 2;
            int n1  = (tid + 256) >> 2;
            int kq0 = (tid & 3) * 4;
            pbx0 = *reinterpret_cast<const float4*>(&W1[(size_t)n0 * INF + k0 + kq0]);
            pbx1 = *reinterpret_cast<const float4*>(&W1[(size_t)n1 * INF + k0 + kq0]);
        }

        unsigned aF[3][2][4];
        #pragma unroll
        for (int s = 0; s < 3; s++)
            #pragma unroll
            for (int mt = 0; mt < 2; mt++) {
                const unsigned short* ab = &As[buf][s][(wm * 32 + mt * 16) * ASTRIDE];
                aF[s][mt][0] = *reinterpret_cast<const unsigned*>(&ab[(g)     * ASTRIDE + tg * 2]);
                aF[s][mt][1] = *reinterpret_cast<const unsigned*>(&ab[(g + 8) * ASTRIDE + tg * 2]);
                aF[s][mt][2] = *reinterpret_cast<const unsigned*>(&ab[(g)     * ASTRIDE + tg * 2 + 8]);
                aF[s][mt][3] = *reinterpret_cast<const unsigned*>(&ab[(g + 8) * ASTRIDE + tg * 2 + 8]);
            }
        unsigned bF[3][4][2];
        #pragma unroll
        for (int s = 0; s < 3; s++)
            #pragma unroll
            for (int nt = 0; nt < 4; nt++) {
                const unsigned short* bb = &Bs[buf][s][(wn * 32 + nt * 8 + g) * ASTRIDE];
                bF[s][nt][0] = *reinterpret_cast<const unsigned*>(&bb[tg * 2]);
                bF[s][nt][1] = *reinterpret_cast<const unsigned*>(&bb[tg * 2 + 8]);
            }

        #pragma unroll
        for (int p = 0; p < 6; p++) {
            const int PI[6] = {0, 0, 1, 0, 1, 2};
            const int PJ[6] = {0, 1, 0, 2, 1, 0};
            int i = PI[p], j = PJ[p];
            #pragma unroll
            for (int mt = 0; mt < 2; mt++)
                #pragma unroll
                for (int nt = 0; nt < 4; nt++)
                    mma_bf16(acc[mt][nt], aF[i][mt], bF[j][nt]);
        }

        if (kc < KCHUNKS - 1) {
            int ob = buf ^ 1;
            float av[4] = {pax.x, pax.y, pax.z, pax.w};
            #pragma unroll
            for (int i = 0; i < 4; i++) {
                unsigned short h0, h1, h2;
                split3(av[i], h0, h1, h2);
                As[ob][0][sm * ASTRIDE + skq + i] = h0;
                As[ob][1][sm * ASTRIDE + skq + i] = h1;
                As[ob][2][sm * ASTRIDE + skq + i] = h2;
            }
            int n0  = tid >> 2;
            int n1  = (tid + 256) >> 2;
            int kq0 = (tid & 3) * 4;
            float bv0[4] = {pbx0.x, pbx0.y, pbx0.z, pbx0.w};
            float bv1[4] = {pbx1.x, pbx1.y, pbx1.z, pbx1.w};
            #pragma unroll
            for (int i = 0; i < 4; i++) {
                unsigned short h0, h1, h2;
                split3(bv0[i], h0, h1, h2);
                Bs[ob][0][n0 * ASTRIDE + kq0 + i] = h0;
                Bs[ob][1][n0 * ASTRIDE + kq0 + i] = h1;
                Bs[ob][2][n0 * ASTRIDE + kq0 + i] = h2;
                split3(bv1[i], h0, h1, h2);
                Bs[ob][0][n1 * ASTRIDE + kq0 + i] = h0;
                Bs[ob][1][n1 * ASTRIDE + kq0 + i] = h1;
                Bs[ob][2][n1 * ASTRIDE + kq0 + i] = h2;
            }
        }
        __syncthreads();
        buf ^= 1;
    }

    // ---- epilogue: + b1, LIF with margin tracking, write spikes ----
    float cur[2][4][4];
    #pragma unroll
    for (int nt = 0; nt < 4; nt++) {
        float2 bv = *reinterpret_cast<const float2*>(&b1[wn * 32 + nt * 8 + tg * 2]);
        #pragma unroll
        for (int mt = 0; mt < 2; mt++) {
            cur[mt][nt][0] = acc[mt][nt][0] + bv.x;
            cur[mt][nt][1] = acc[mt][nt][1] + bv.y;
            cur[mt][nt][2] = acc[mt][nt][2] + bv.x;
            cur[mt][nt][3] = acc[mt][nt][3] + bv.y;
        }
    }

    float mem[2][4][4];
    unsigned badm[2][4];      // 4-bit risk mask per (mt,nt)
    #pragma unroll
    for (int mt = 0; mt < 2; mt++)
        #pragma unroll
        for (int nt = 0; nt < 4; nt++) {
            badm[mt][nt] = 0u;
            #pragma unroll
            for (int r = 0; r < 4; r++) mem[mt][nt][r] = 0.0f;
        }

    for (int t = 0; t < TSTEPS; t++) {
        float* pt = out_spk + (size_t)t * ((size_t)BATCH * HID);
        #pragma unroll
        for (int mt = 0; mt < 2; mt++) {
            int r0 = m0 + wm * 32 + mt * 16 + g;
            #pragma unroll
            for (int nt = 0; nt < 4; nt++) {
                int n = wn * 32 + nt * 8 + tg * 2;
                float s[4];
                #pragma unroll
                for (int r = 0; r < 4; r++) {
                    float m = fmaf(mem[mt][nt][r], DECAYF, cur[mt][nt][r]);
                    if (fabsf(m - THRESHF) < EPSM) badm[mt][nt] |= (1u << r);
                    s[r] = (m > THRESHF) ? 1.0f : 0.0f;
                    mem[mt][nt][r] = (s[r] != 0.0f) ? 0.0f : m;
                }
                float2 v0 = {s[0], s[1]};
                float2 v1 = {s[2], s[3]};
                *reinterpret_cast<float2*>(&pt[(size_t)r0 * HID + n])       = v0;
                *reinterpret_cast<float2*>(&pt[(size_t)(r0 + 8) * HID + n]) = v1;
            }
        }
    }

    // ---- enqueue risky elements ----
    #pragma unroll
    for (int mt = 0; mt < 2; mt++)
        #pragma unroll
        for (int nt = 0; nt < 4; nt++) {
            if (badm[mt][nt]) {
                #pragma unroll
                for (int r = 0; r < 4; r++)
                    if (badm[mt][nt] & (1u << r)) {
                        int row = m0 + wm * 32 + mt * 16 + g + ((r >> 1) ? 8 : 0);
                        int col = wn * 32 + nt * 8 + tg * 2 + (r & 1);
                        unsigned pos = atomicAdd(&g_fix_cnt, 1u);
                        if (pos < FIXCAP)
                            g_fix_list[pos] = (unsigned)(row * HID + col);
                    }
            }
        }
}

// ---------------------------------------------------------------------------
// K1b fixup: exact sequential-k fp32 recompute for risky elements (bitwise
// identical to the R1 recipe: ascending-k fmaf chain, then +b1).
// ---------------------------------------------------------------------------
__global__ __launch_bounds__(128) void k1_fixup(
    const float* __restrict__ x, const float* __restrict__ W1,
    const float* __restrict__ b1, float* __restrict__ out_spk)
{
    const unsigned cnt = min(*(volatile unsigned*)&g_fix_cnt, (unsigned)FIXCAP);
    const int stride = gridDim.x * blockDim.x;

    for (unsigned i = blockIdx.x * blockDim.x + threadIdx.x; i < cnt; i += stride) {
        unsigned idx = g_fix_list[i];
        int b = idx >> 7;          // /HID
        int j = idx & (HID - 1);

        const float* xr = x  + (size_t)b * INF;
        const float* wr = W1 + (size_t)j * INF;
        float a = 0.0f;
        for (int k = 0; k < INF; k++)
            a = fmaf(__ldg(&xr[k]), __ldg(&wr[k]), a);
        float curv = a + __ldg(&b1[j]);

        float m = 0.0f;
        for (int t = 0; t < TSTEPS; t++) {
            m = fmaf(m, DECAYF, curv);
            float s = (m > THRESHF) ? 1.0f : 0.0f;
            out_spk[(size_t)t * ((size_t)BATCH * HID) + idx] = s;
            m = (s != 0.0f) ? 0.0f : m;
        }
    }
}

// ---------------------------------------------------------------------------
// K3 / K4: verbatim R1 (proven exact).
// ---------------------------------------------------------------------------
__global__ __launch_bounds__(256) void k3_gemm2(
    const float* __restrict__ spk, const float* __restrict__ W2)
{
    __shared__ float sh[256][33];
    __shared__ float W2s[NCLS * HID];

    const int tid = threadIdx.x;
    for (int i = tid; i < NCLS * HID; i += 256) W2s[i] = W2[i];

    const size_t row0 = (size_t)blockIdx.x * 256;
    float acc[NCLS];
    #pragma unroll
    for (int o = 0; o < NCLS; o++) acc[o] = 0.0f;

    for (int jc = 0; jc < 4; jc++) {
        __syncthreads();
        #pragma unroll
        for (int s4 = 0; s4 < 8; s4++) {
            int f = tid + s4 * 256;
            int r = f >> 3;
            int q = f & 7;
            float4 v = *reinterpret_cast<const float4*>(
                &spk[(row0 + r) * HID + jc * 32 + q * 4]);
            sh[r][q * 4 + 0] = v.x; sh[r][q * 4 + 1] = v.y;
            sh[r][q * 4 + 2] = v.z; sh[r][q * 4 + 3] = v.w;
        }
        __syncthreads();
        #pragma unroll
        for (int j = 0; j < 32; j++) {
            float s = sh[tid][j];
            #pragma unroll
            for (int o = 0; o < NCLS; o++)
                acc[o] = fmaf(s, W2s[o * HID + jc * 32 + j], acc[o]);
        }
    }

    const size_t r = row0 + tid;
    #pragma unroll
    for (int o = 0; o < NCLS; o++)
        g_c2[r * NCLS + o] = acc[o];
}

__global__ __launch_bounds__(256) void k4_lif2(
    const float* __restrict__ b2, float* __restrict__ outp)
{
    const int id = blockIdx.x * blockDim.x + threadIdx.x;
    const int o = id % NCLS;
    const float bias = __ldg(&b2[o]);

    float mem = 0.0f, acc = 0.0f;
    #pragma unroll
    for (int t = 0; t < TSTEPS; t++) {
        float v = fmaf(mem, DECAYF, g_c2[(size_t)t * (BATCH * NCLS) + id]);
        v = v + bias;
        float s = (v > THRESHF) ? 1.0f : 0.0f;
        acc += s;
        mem = (s != 0.0f) ? 0.0f : v;
    }
    outp[id] = acc;
}

// ---------------------------------------------------------------------------
extern "C" void kernel_launch(void* const* d_in, const int* in_sizes, int n_in,
                              void* d_out, int out_size)
{
    const float* x  = (const float*)d_in[0];
    const float* W1 = (const float*)d_in[1];
    const float* b1 = (const float*)d_in[2];
    const float* W2 = (const float*)d_in[3];
    const float* b2 = (const float*)d_in[4];
    float* out = (float*)d_out;

    float* out_output = out;                          // [BATCH, NCLS]
    float* out_spk    = out + (size_t)BATCH * NCLS;   // [T, BATCH, HID]

    k0_zero<<<1, 1>>>();
    k1_mma<<<BATCH / 64, 256>>>(x, W1, b1, out_spk);
    k1_fixup<<<256, 128>>>(x, W1, b1, out_spk);
    k3_gemm2<<<(TSTEPS * BATCH) / 256, 256>>>(out_spk, W2);
    k4_lif2<<<(BATCH * NCLS) / 256, 256>>>(b2, out_output);
}

// round 5
// speedup vs baseline: 1.3431x; 1.2428x over previous
#include <cuda_runtime.h>
#include <cuda_bf16.h>

#define BATCH   32768
#define HID     128
#define INF     784
#define NCLS    10
#define TSTEPS  20

#define DECAYF  0.25f
#define THRESHF 1.0f
#define EPSM    2e-4f

#define KCHUNKS (INF / 16)      // 49
#define FIXCAP  (1 << 21)

// Scratch (device globals)
__device__ float    g_c2[(size_t)TSTEPS * BATCH * NCLS];
__device__ unsigned g_fix_list[FIXCAP];
__device__ unsigned g_fix_cnt;
__device__ __align__(16) unsigned short g_w1a[HID * INF];   // bf16 hi plane
__device__ __align__(16) unsigned short g_w1b[HID * INF];   // bf16 lo plane

// ---------------------------------------------------------------------------
__device__ __forceinline__ void split2(float v, unsigned short& h0, unsigned short& h1)
{
    __nv_bfloat16 b0 = __float2bfloat16_rn(v);
    float r = v - __bfloat162float(b0);
    __nv_bfloat16 b1 = __float2bfloat16_rn(r);
    h0 = __bfloat16_as_ushort(b0);
    h1 = __bfloat16_as_ushort(b1);
}

__device__ __forceinline__ void mma_bf16(float* d, const unsigned* a, const unsigned* b)
{
    asm volatile(
        "mma.sync.aligned.m16n8k16.row.col.f32.bf16.bf16.f32 "
        "{%0,%1,%2,%3}, {%4,%5,%6,%7}, {%8,%9}, {%0,%1,%2,%3};"
        : "+f"(d[0]), "+f"(d[1]), "+f"(d[2]), "+f"(d[3])
        : "r"(a[0]), "r"(a[1]), "r"(a[2]), "r"(a[3]), "r"(b[0]), "r"(b[1]));
}

__global__ void k0_init(const float* __restrict__ W1)
{
    if (blockIdx.x == 0 && threadIdx.x == 0) g_fix_cnt = 0;
    int i = blockIdx.x * blockDim.x + threadIdx.x;
    if (i < HID * INF) {
        unsigned short h0, h1;
        split2(W1[i], h0, h1);
        g_w1a[i] = h0;
        g_w1b[i] = h1;
    }
}

// ---------------------------------------------------------------------------
// K1: cur1 via bf16x2-split (3 tensor-core products), fused LIF epilogue with
// margin tracking. Tile M=64 x N=128, 256 threads = 8 warps (2m x 4n).
// ---------------------------------------------------------------------------
#define ASTRIDE 24   // ushorts per smem row (48B: 16B-aligned, conflict-free frags)

__global__ __launch_bounds__(256) void k1_mma(
    const float* __restrict__ x, const float* __restrict__ b1,
    float* __restrict__ out_spk)
{
    __shared__ unsigned short As[2][2][64  * ASTRIDE];
    __shared__ unsigned short Bs[2][2][128 * ASTRIDE];

    const int tid  = threadIdx.x;
    const int lane = tid & 31;
    const int wid  = tid >> 5;
    const int g    = lane >> 2;
    const int tg   = lane & 3;
    const int wm   = wid >> 2;
    const int wn   = wid & 3;
    const int m0   = blockIdx.x * 64;

    const int sm  = tid >> 2;           // A stage row 0..63
    const int skq = (tid & 3) * 4;      // A stage k 0,4,8,12
    const int bn  = tid >> 1;           // B stage n 0..127
    const int bkh = (tid & 1) * 8;      // B stage k half

    float acc[2][4][4];
    #pragma unroll
    for (int mt = 0; mt < 2; mt++)
        #pragma unroll
        for (int nt = 0; nt < 4; nt++)
            #pragma unroll
            for (int r = 0; r < 4; r++) acc[mt][nt][r] = 0.0f;

    // ---- prologue: stage chunk 0 into buf 0 ----
    {
        float4 ax = *reinterpret_cast<const float4*>(&x[(size_t)(m0 + sm) * INF + skq]);
        float av[4] = {ax.x, ax.y, ax.z, ax.w};
        unsigned short p0[4], p1[4];
        #pragma unroll
        for (int i = 0; i < 4; i++) split2(av[i], p0[i], p1[i]);
        *reinterpret_cast<uint2*>(&As[0][0][sm * ASTRIDE + skq]) = *reinterpret_cast<uint2*>(p0);
        *reinterpret_cast<uint2*>(&As[0][1][sm * ASTRIDE + skq]) = *reinterpret_cast<uint2*>(p1);

        uint4 va = *reinterpret_cast<const uint4*>(&g_w1a[bn * INF + bkh]);
        uint4 vb = *reinterpret_cast<const uint4*>(&g_w1b[bn * INF + bkh]);
        *reinterpret_cast<uint4*>(&Bs[0][0][bn * ASTRIDE + bkh]) = va;
        *reinterpret_cast<uint4*>(&Bs[0][1][bn * ASTRIDE + bkh]) = vb;
    }
    __syncthreads();

    int buf = 0;
    for (int kc = 0; kc < KCHUNKS; kc++) {
        // prefetch next chunk
        float4 pax;
        uint4 pba, pbb;
        if (kc < KCHUNKS - 1) {
            int k0 = (kc + 1) * 16;
            pax = *reinterpret_cast<const float4*>(&x[(size_t)(m0 + sm) * INF + k0 + skq]);
            pba = *reinterpret_cast<const uint4*>(&g_w1a[bn * INF + k0 + bkh]);
            pbb = *reinterpret_cast<const uint4*>(&g_w1b[bn * INF + k0 + bkh]);
        }

        // fragments
        unsigned aF[2][2][4];
        #pragma unroll
        for (int s = 0; s < 2; s++)
            #pragma unroll
            for (int mt = 0; mt < 2; mt++) {
                const unsigned short* ab = &As[buf][s][(wm * 32 + mt * 16) * ASTRIDE];
                aF[s][mt][0] = *reinterpret_cast<const unsigned*>(&ab[(g)     * ASTRIDE + tg * 2]);
                aF[s][mt][1] = *reinterpret_cast<const unsigned*>(&ab[(g + 8) * ASTRIDE + tg * 2]);
                aF[s][mt][2] = *reinterpret_cast<const unsigned*>(&ab[(g)     * ASTRIDE + tg * 2 + 8]);
                aF[s][mt][3] = *reinterpret_cast<const unsigned*>(&ab[(g + 8) * ASTRIDE + tg * 2 + 8]);
            }
        unsigned bF[2][4][2];
        #pragma unroll
        for (int s = 0; s < 2; s++)
            #pragma unroll
            for (int nt = 0; nt < 4; nt++) {
                const unsigned short* bb = &Bs[buf][s][(wn * 32 + nt * 8 + g) * ASTRIDE];
                bF[s][nt][0] = *reinterpret_cast<const unsigned*>(&bb[tg * 2]);
                bF[s][nt][1] = *reinterpret_cast<const unsigned*>(&bb[tg * 2 + 8]);
            }

        // 3 split-products: a0b0, a0b1, a1b0
        #pragma unroll
        for (int p = 0; p < 3; p++) {
            const int PI[3] = {0, 0, 1};
            const int PJ[3] = {0, 1, 0};
            int i = PI[p], j = PJ[p];
            #pragma unroll
            for (int mt = 0; mt < 2; mt++)
                #pragma unroll
                for (int nt = 0; nt < 4; nt++)
                    mma_bf16(acc[mt][nt], aF[i][mt], bF[j][nt]);
        }

        // stage prefetched chunk into other buffer
        if (kc < KCHUNKS - 1) {
            int ob = buf ^ 1;
            float av[4] = {pax.x, pax.y, pax.z, pax.w};
            unsigned short p0[4], p1[4];
            #pragma unroll
            for (int i = 0; i < 4; i++) split2(av[i], p0[i], p1[i]);
            *reinterpret_cast<uint2*>(&As[ob][0][sm * ASTRIDE + skq]) = *reinterpret_cast<uint2*>(p0);
            *reinterpret_cast<uint2*>(&As[ob][1][sm * ASTRIDE + skq]) = *reinterpret_cast<uint2*>(p1);
            *reinterpret_cast<uint4*>(&Bs[ob][0][bn * ASTRIDE + bkh]) = pba;
            *reinterpret_cast<uint4*>(&Bs[ob][1][bn * ASTRIDE + bkh]) = pbb;
        }
        __syncthreads();
        buf ^= 1;
    }

    // ---- epilogue: + b1, LIF with margin tracking, write spikes ----
    float cur[2][4][4];
    #pragma unroll
    for (int nt = 0; nt < 4; nt++) {
        float2 bv = *reinterpret_cast<const float2*>(&b1[wn * 32 + nt * 8 + tg * 2]);
        #pragma unroll
        for (int mt = 0; mt < 2; mt++) {
            cur[mt][nt][0] = acc[mt][nt][0] + bv.x;
            cur[mt][nt][1] = acc[mt][nt][1] + bv.y;
            cur[mt][nt][2] = acc[mt][nt][2] + bv.x;
            cur[mt][nt][3] = acc[mt][nt][3] + bv.y;
        }
    }

    float mem[2][4][4];
    unsigned badm[2][4];
    #pragma unroll
    for (int mt = 0; mt < 2; mt++)
        #pragma unroll
        for (int nt = 0; nt < 4; nt++) {
            badm[mt][nt] = 0u;
            #pragma unroll
            for (int r = 0; r < 4; r++) mem[mt][nt][r] = 0.0f;
        }

    for (int t = 0; t < TSTEPS; t++) {
        float* pt = out_spk + (size_t)t * ((size_t)BATCH * HID);
        #pragma unroll
        for (int mt = 0; mt < 2; mt++) {
            int r0 = m0 + wm * 32 + mt * 16 + g;
            #pragma unroll
            for (int nt = 0; nt < 4; nt++) {
                int n = wn * 32 + nt * 8 + tg * 2;
                float s[4];
                #pragma unroll
                for (int r = 0; r < 4; r++) {
                    float m = fmaf(mem[mt][nt][r], DECAYF, cur[mt][nt][r]);
                    if (fabsf(m - THRESHF) < EPSM) badm[mt][nt] |= (1u << r);
                    s[r] = (m > THRESHF) ? 1.0f : 0.0f;
                    mem[mt][nt][r] = (s[r] != 0.0f) ? 0.0f : m;
                }
                float2 v0 = {s[0], s[1]};
                float2 v1 = {s[2], s[3]};
                *reinterpret_cast<float2*>(&pt[(size_t)r0 * HID + n])       = v0;
                *reinterpret_cast<float2*>(&pt[(size_t)(r0 + 8) * HID + n]) = v1;
            }
        }
    }

    #pragma unroll
    for (int mt = 0; mt < 2; mt++)
        #pragma unroll
        for (int nt = 0; nt < 4; nt++)
            if (badm[mt][nt]) {
                #pragma unroll
                for (int r = 0; r < 4; r++)
                    if (badm[mt][nt] & (1u << r)) {
                        int row = m0 + wm * 32 + mt * 16 + g + ((r >> 1) ? 8 : 0);
                        int col = wn * 32 + nt * 8 + tg * 2 + (r & 1);
                        unsigned pos = atomicAdd(&g_fix_cnt, 1u);
                        if (pos < FIXCAP)
                            g_fix_list[pos] = (unsigned)(row * HID + col);
                    }
            }
}

// ---------------------------------------------------------------------------
// K1b fixup: exact sequential-k fp32 recompute (bitwise R1 recipe).
// ---------------------------------------------------------------------------
__global__ __launch_bounds__(128) void k1_fixup(
    const float* __restrict__ x, const float* __restrict__ W1,
    const float* __restrict__ b1, float* __restrict__ out_spk)
{
    const unsigned cnt = min(*(volatile unsigned*)&g_fix_cnt, (unsigned)FIXCAP);
    const int stride = gridDim.x * blockDim.x;

    for (unsigned i = blockIdx.x * blockDim.x + threadIdx.x; i < cnt; i += stride) {
        unsigned idx = g_fix_list[i];
        int b = idx >> 7;
        int j = idx & (HID - 1);

        const float* xr = x  + (size_t)b * INF;
        const float* wr = W1 + (size_t)j * INF;
        float a = 0.0f;
        for (int k = 0; k < INF; k++)
            a = fmaf(__ldg(&xr[k]), __ldg(&wr[k]), a);
        float curv = a + __ldg(&b1[j]);

        float m = 0.0f;
        for (int t = 0; t < TSTEPS; t++) {
            m = fmaf(m, DECAYF, curv);
            float s = (m > THRESHF) ? 1.0f : 0.0f;
            out_spk[(size_t)t * ((size_t)BATCH * HID) + idx] = s;
            m = (s != 0.0f) ? 0.0f : m;
        }
    }
}

// ---------------------------------------------------------------------------
// K3: c2 = spk @ W2^T.  W2 transposed in smem [j][o pad 12] -> 3 vector LDS
// + 10 FMA per j (same ascending-j fmaf chain as R1 -> bitwise identical).
// ---------------------------------------------------------------------------
__global__ __launch_bounds__(256) void k3_gemm2(
    const float* __restrict__ spk, const float* __restrict__ W2)
{
    __shared__ float sh[256][33];
    __shared__ float W2t[HID][12];

    const int tid = threadIdx.x;
    for (int i = tid; i < HID * NCLS; i += 256) {
        int j = i / NCLS;
        int o = i - j * NCLS;
        W2t[j][o] = W2[o * HID + j];
    }

    const size_t row0 = (size_t)blockIdx.x * 256;
    float acc[NCLS];
    #pragma unroll
    for (int o = 0; o < NCLS; o++) acc[o] = 0.0f;

    for (int jc = 0; jc < 4; jc++) {
        __syncthreads();
        #pragma unroll
        for (int s4 = 0; s4 < 8; s4++) {
            int f = tid + s4 * 256;
            int r = f >> 3;
            int q = f & 7;
            float4 v = *reinterpret_cast<const float4*>(
                &spk[(row0 + r) * HID + jc * 32 + q * 4]);
            sh[r][q * 4 + 0] = v.x; sh[r][q * 4 + 1] = v.y;
            sh[r][q * 4 + 2] = v.z; sh[r][q * 4 + 3] = v.w;
        }
        __syncthreads();
        #pragma unroll
        for (int j = 0; j < 32; j++) {
            float s = sh[tid][j];
            const float* wr = W2t[jc * 32 + j];
            float4 w0 = *reinterpret_cast<const float4*>(wr);
            float4 w1 = *reinterpret_cast<const float4*>(wr + 4);
            float2 w2 = *reinterpret_cast<const float2*>(wr + 8);
            acc[0] = fmaf(s, w0.x, acc[0]);
            acc[1] = fmaf(s, w0.y, acc[1]);
            acc[2] = fmaf(s, w0.z, acc[2]);
            acc[3] = fmaf(s, w0.w, acc[3]);
            acc[4] = fmaf(s, w1.x, acc[4]);
            acc[5] = fmaf(s, w1.y, acc[5]);
            acc[6] = fmaf(s, w1.z, acc[6]);
            acc[7] = fmaf(s, w1.w, acc[7]);
            acc[8] = fmaf(s, w2.x, acc[8]);
            acc[9] = fmaf(s, w2.y, acc[9]);
        }
    }

    const size_t r = row0 + tid;
    #pragma unroll
    for (int o = 0; o < NCLS; o++)
        g_c2[r * NCLS + o] = acc[o];
}

// ---------------------------------------------------------------------------
__global__ __launch_bounds__(256) void k4_lif2(
    const float* __restrict__ b2, float* __restrict__ outp)
{
    const int id = blockIdx.x * blockDim.x + threadIdx.x;
    const int o = id % NCLS;
    const float bias = __ldg(&b2[o]);

    float mem = 0.0f, acc = 0.0f;
    #pragma unroll
    for (int t = 0; t < TSTEPS; t++) {
        float v = fmaf(mem, DECAYF, g_c2[(size_t)t * (BATCH * NCLS) + id]);
        v = v + bias;
        float s = (v > THRESHF) ? 1.0f : 0.0f;
        acc += s;
        mem = (s != 0.0f) ? 0.0f : v;
    }
    outp[id] = acc;
}

// ---------------------------------------------------------------------------
extern "C" void kernel_launch(void* const* d_in, const int* in_sizes, int n_in,
                              void* d_out, int out_size)
{
    const float* x  = (const float*)d_in[0];
    const float* W1 = (const float*)d_in[1];
    const float* b1 = (const float*)d_in[2];
    const float* W2 = (const float*)d_in[3];
    const float* b2 = (const float*)d_in[4];
    float* out = (float*)d_out;

    float* out_output = out;
    float* out_spk    = out + (size_t)BATCH * NCLS;

    k0_init<<<(HID * INF + 255) / 256, 256>>>(W1);
    k1_mma<<<BATCH / 64, 256>>>(x, b1, out_spk);
    k1_fixup<<<256, 128>>>(x, W1, b1, out_spk);
    k3_gemm2<<<(TSTEPS * BATCH) / 256, 256>>>(out_spk, W2);
    k4_lif2<<<(BATCH * NCLS) / 256, 256>>>(b2, out_output);
}